// round 15
// baseline (speedup 1.0000x reference)
#include <cuda_runtime.h>
#include <cuda_bf16.h>
#include <math.h>
#include <stdint.h>

namespace cfg {
constexpr int Bn = 64, LT = 1024, LV = 576, E = 768, Kd = 128, NP = 8;
}
using bf16 = __nv_bfloat16;

__device__ __forceinline__ void split2(float v, bf16& h, bf16& l) {
    h = __float2bfloat16(v);
    l = __float2bfloat16(v - __bfloat162float(h));
}
__device__ __forceinline__ uint32_t pack_bf2(bf16 a, bf16 b) {
    union { bf16 h[2]; uint32_t u; } w; w.h[0] = a; w.h[1] = b; return w.u;
}
__device__ __forceinline__ void mma16816(float* d, const uint32_t* a, const uint32_t* b) {
    asm volatile("mma.sync.aligned.m16n8k16.row.col.f32.bf16.bf16.f32 "
        "{%0,%1,%2,%3}, {%4,%5,%6,%7}, {%8,%9}, {%0,%1,%2,%3};"
        : "+f"(d[0]), "+f"(d[1]), "+f"(d[2]), "+f"(d[3])
        : "r"(a[0]), "r"(a[1]), "r"(a[2]), "r"(a[3]), "r"(b[0]), "r"(b[1]));
}
__device__ __forceinline__ void ldm_x4(uint32_t* r, uint32_t sa) {
    asm volatile("ldmatrix.sync.aligned.m8n8.x4.shared.b16 {%0,%1,%2,%3}, [%4];"
        : "=r"(r[0]), "=r"(r[1]), "=r"(r[2]), "=r"(r[3]) : "r"(sa));
}
__device__ __forceinline__ void ldm_x4t(uint32_t* r, uint32_t sa) {
    asm volatile("ldmatrix.sync.aligned.m8n8.x4.trans.shared.b16 {%0,%1,%2,%3}, [%4];"
        : "=r"(r[0]), "=r"(r[1]), "=r"(r[2]), "=r"(r[3]) : "r"(sa));
}
__device__ __forceinline__ uint32_t smem_u32(const void* p) {
    uint32_t a;
    asm("{ .reg .u64 t; cvta.to.shared.u64 t, %1; cvt.u32.u64 %0, t; }" : "=r"(a) : "l"(p));
    return a;
}
#define CP_ASYNC16(s, g) \
    asm volatile("cp.async.cg.shared.global [%0], [%1], 16;" :: "r"(s), "l"(g))
#define CP_COMMIT() asm volatile("cp.async.commit_group;")
#define CP_WAIT2()  asm volatile("cp.async.wait_group 2;")
#define CP_WAIT1()  asm volatile("cp.async.wait_group 1;")
#define CP_WAIT0()  asm volatile("cp.async.wait_group 0;")

#define SWZ64(row, kb)  ((uint32_t)((row) * 64  + ((kb) ^ (((row) & 3) << 4))))
#define SWZ256(row, kb) ((uint32_t)((row) * 256 + ((kb) ^ (((row) & 7) << 4))))

// ===================== globals =====================
#define DEV_BF16(n, c) __device__ __align__(256) bf16 n[c]
DEV_BF16(g_wbhi, 768 * 768);       DEV_BF16(g_wblo, 768 * 768);
DEV_BF16(g_wqhi, 768 * 128);       DEV_BF16(g_wqlo, 768 * 128);
DEV_BF16(g_wvhi, 768 * 128);       DEV_BF16(g_wvlo, 768 * 128);
DEV_BF16(g_wqqhi, 64 * 1024 * 128); DEV_BF16(g_wqqlo, 64 * 1024 * 128);
DEV_BF16(g_wvvhi, 64 * 576 * 128);  DEV_BF16(g_wvvlo, 64 * 576 * 128);
DEV_BF16(g_A1hi, 64 * 768 * 128);   DEV_BF16(g_A1lo, 64 * 768 * 128);
DEV_BF16(g_M1hi, 64 * 768 * 128);   DEV_BF16(g_M1lo, 64 * 768 * 128);
DEV_BF16(g_A2hi, 64 * 768 * 128);   DEV_BF16(g_A2lo, 64 * 768 * 128);
DEV_BF16(g_Hhi, 64 * 768 * 128);    DEV_BF16(g_Hlo, 64 * 768 * 128);
__device__ float g_sv[cfg::Bn * cfg::LV];
__device__ float g_sq[cfg::Bn * cfg::LT];
__device__ float g_ctxp[cfg::Bn * cfg::NP * cfg::E];

// ===================== conversion (weights only) =====================
__global__ void conv_flat(const float* __restrict__ X,
                          bf16* __restrict__ hi, bf16* __restrict__ lo, long n4)
{
    long i = (long)blockIdx.x * blockDim.x + threadIdx.x;
    if (i >= n4) return;
    float4 v = ((const float4*)X)[i];
    union { bf16 h[4]; uint2 u; } H, L;
    split2(v.x, H.h[0], L.h[0]); split2(v.y, H.h[1], L.h[1]);
    split2(v.z, H.h[2], L.h[2]); split2(v.w, H.h[3], L.h[3]);
    ((uint2*)hi)[i] = H.u; ((uint2*)lo)[i] = L.u;
}

// ===================== merged-pair HMMA GEMM =====================
// AF32: A fp32 via LDG->regs->split->STS, 3-stage A-bf16 + 3-stage B, 1 sync/chunk.
//   layout: [A0 16K][A1 16K][A2 16K][B0 16K][B1 16K][B2 16K]  (Bh +0, Bl +8K)
// !AF32: A bf16 hi/lo, 3 stages of 32K ([Ah 8K|Al 8K|Bh 8K|Bl 8K]).
constexpr int MATB = 8192, STAGEB = 4 * MATB;
static constexpr int SMEM_MMA_BYTES = 98304;

struct GArgs {
    const float* Af;
    const bf16 *Ahi, *Alo;
    const bf16 *Bhi, *Blo;
    long sA, sB, sHL, sU, sS;
    bf16 *Chi, *Clo;
    const bf16 *Uhi, *Ulo;
    const float* wh;
    float* Sout;
    int Ktot, Mvalid, transA, Mclamp;
};

template <bool AF32, bool OUTHL, bool OUTS>
__global__ void __launch_bounds__(256, 2) mma_gemm(GArgs a0, GArgs a1, int splitX)
{
    extern __shared__ __align__(16) char sm[];
    __shared__ float s_wh[128];
    const uint32_t smb = smem_u32(sm);

    const GArgs& A = (blockIdx.x < (unsigned)splitX) ? a0 : a1;
    const int bx = (blockIdx.x < (unsigned)splitX) ? blockIdx.x : blockIdx.x - splitX;
    const int tid = threadIdx.x, lane = tid & 31, wid = tid >> 5;
    const int wm = wid & 1, wn = wid >> 1, g = lane >> 2, t = lane & 3;
    const long z = blockIdx.z;
    const int m0 = bx * 128, Ktot = A.Ktot;
    const bool trA = (A.transA != 0);

    if (OUTS && tid < 128) s_wh[tid] = A.wh[tid];

    const float* Af = nullptr;
    const bf16 *Ah = nullptr, *Al = nullptr;
    if (AF32) {
        Af = A.Af + z * A.sA;
    } else {
        Ah = A.Ahi + z * A.sA + (trA ? 0 : (long)m0 * 768);
        Al = A.Alo + z * A.sA + (trA ? 0 : (long)m0 * 768);
    }
    const bf16* Bh = A.Bhi + z * A.sB;
    const bf16* Bl = A.Blo + z * A.sB;

    float acc[4][4][4];
#pragma unroll
    for (int i = 0; i < 4; i++)
#pragma unroll
        for (int j = 0; j < 4; j++)
#pragma unroll
            for (int q = 0; q < 4; q++) acc[i][j][q] = 0.f;

    const int nch = Ktot >> 5;
    // per-thread 16B-unit coords (bf16 tile space)
    const int nr0 = (tid * 2) >> 2, nc0 = ((tid * 2) & 3) * 16;
    const int nr1 = (tid * 2 + 1) >> 2, nc1 = ((tid * 2 + 1) & 3) * 16;
    const int tr0 = (tid * 2) >> 4, tc0 = ((tid * 2) & 15) * 16;
    const int tr1 = (tid * 2 + 1) >> 4, tc1 = ((tid * 2 + 1) & 15) * 16;

    float4 pa[4];   // staged fp32 A fragment (AF32 path)

    auto ldgA = [&](int c) {
        const int k0 = c << 5;
        if (trA) {
            const float* p0 = Af + (long)(k0 + tr0) * 768 + m0 + tc0 / 2;
            const float* p1 = Af + (long)(k0 + tr1) * 768 + m0 + tc1 / 2;
            pa[0] = *(const float4*)p0; pa[1] = *(const float4*)(p0 + 4);
            pa[2] = *(const float4*)p1; pa[3] = *(const float4*)(p1 + 4);
        } else {
            int r0c = m0 + nr0; if (r0c >= A.Mclamp) r0c = A.Mclamp - 1;
            int r1c = m0 + nr1; if (r1c >= A.Mclamp) r1c = A.Mclamp - 1;
            const float* p0 = Af + (long)r0c * 768 + k0 + nc0 / 2;
            const float* p1 = Af + (long)r1c * 768 + k0 + nc1 / 2;
            pa[0] = *(const float4*)p0; pa[1] = *(const float4*)(p0 + 4);
            pa[2] = *(const float4*)p1; pa[3] = *(const float4*)(p1 + 4);
        }
    };
    auto stsA = [&](int c) {
        char* ab = sm + (c % 3) * 16384;
#pragma unroll
        for (int u = 0; u < 2; u++) {
            float f[8] = {pa[2 * u].x, pa[2 * u].y, pa[2 * u].z, pa[2 * u].w,
                          pa[2 * u + 1].x, pa[2 * u + 1].y, pa[2 * u + 1].z, pa[2 * u + 1].w};
            bf16 h[8], l[8];
#pragma unroll
            for (int j = 0; j < 8; j++) split2(f[j], h[j], l[j]);
            uint4 H = make_uint4(pack_bf2(h[0], h[1]), pack_bf2(h[2], h[3]),
                                 pack_bf2(h[4], h[5]), pack_bf2(h[6], h[7]));
            uint4 L = make_uint4(pack_bf2(l[0], l[1]), pack_bf2(l[2], l[3]),
                                 pack_bf2(l[4], l[5]), pack_bf2(l[6], l[7]));
            const uint32_t w = trA ? SWZ256(u ? tr1 : tr0, u ? tc1 : tc0)
                                   : SWZ64(u ? nr1 : nr0, u ? nc1 : nc0);
            *(uint4*)(ab + w) = H;
            *(uint4*)(ab + 8192 + w) = L;
        }
    };
    auto cpB = [&](int c, uint32_t bbase) {
        const int k0 = c << 5;
        CP_ASYNC16(bbase + SWZ256(tr0, tc0), Bh + (long)(k0 + tr0) * 128 + tc0 / 2);
        CP_ASYNC16(bbase + SWZ256(tr1, tc1), Bh + (long)(k0 + tr1) * 128 + tc1 / 2);
        CP_ASYNC16(bbase + 8192 + SWZ256(tr0, tc0), Bl + (long)(k0 + tr0) * 128 + tc0 / 2);
        CP_ASYNC16(bbase + 8192 + SWZ256(tr1, tc1), Bl + (long)(k0 + tr1) * 128 + tc1 / 2);
    };
    // bf16-path loader (stage layout [Ah|Al|Bh|Bl] x 32K)
    auto load_bf16 = [&](int c, int stage) {
        const int k0 = c << 5;
        const uint32_t sb = smb + stage * STAGEB;
        if (trA) {
            CP_ASYNC16(sb + SWZ256(tr0, tc0), Ah + (long)(k0 + tr0) * 768 + m0 + tc0 / 2);
            CP_ASYNC16(sb + SWZ256(tr1, tc1), Ah + (long)(k0 + tr1) * 768 + m0 + tc1 / 2);
            CP_ASYNC16(sb + MATB + SWZ256(tr0, tc0), Al + (long)(k0 + tr0) * 768 + m0 + tc0 / 2);
            CP_ASYNC16(sb + MATB + SWZ256(tr1, tc1), Al + (long)(k0 + tr1) * 768 + m0 + tc1 / 2);
        } else {
            CP_ASYNC16(sb + SWZ64(nr0, nc0), Ah + (long)nr0 * 768 + k0 + nc0 / 2);
            CP_ASYNC16(sb + SWZ64(nr1, nc1), Ah + (long)nr1 * 768 + k0 + nc1 / 2);
            CP_ASYNC16(sb + MATB + SWZ64(nr0, nc0), Al + (long)nr0 * 768 + k0 + nc0 / 2);
            CP_ASYNC16(sb + MATB + SWZ64(nr1, nc1), Al + (long)nr1 * 768 + k0 + nc1 / 2);
        }
        CP_ASYNC16(sb + 2 * MATB + SWZ256(tr0, tc0), Bh + (long)(k0 + tr0) * 128 + tc0 / 2);
        CP_ASYNC16(sb + 2 * MATB + SWZ256(tr1, tc1), Bh + (long)(k0 + tr1) * 128 + tc1 / 2);
        CP_ASYNC16(sb + 3 * MATB + SWZ256(tr0, tc0), Bl + (long)(k0 + tr0) * 128 + tc0 / 2);
        CP_ASYNC16(sb + 3 * MATB + SWZ256(tr1, tc1), Bl + (long)(k0 + tr1) * 128 + tc1 / 2);
    };

    const int tr_r = lane & 7, tr_q = lane >> 3;
    const int klB = (tr_q & 1) * 8 + tr_r, nbB = (tr_q >> 1) * 16;
    const int klA = (tr_q >> 1) * 8 + tr_r, mbA = (tr_q & 1) * 16;
    const int aRow = (lane & 7) + ((lane >> 3) & 1) * 8, aKB = (lane >> 4) * 16;

    auto compute_chunk = [&](uint32_t aB, uint32_t bB) {
#pragma unroll
        for (int ks = 0; ks < 2; ks++) {
            uint32_t bh[4][2], bl[4][2];
#pragma unroll
            for (int nfb = 0; nfb < 4; nfb += 2) {
                const int kr = ks * 16 + klB;
                const int nb = (wn * 32 + nfb * 8) * 2 + nbB;
                uint32_t r[4];
                ldm_x4t(r, smb + bB + SWZ256(kr, nb));
                bh[nfb][0] = r[0]; bh[nfb][1] = r[1];
                bh[nfb + 1][0] = r[2]; bh[nfb + 1][1] = r[3];
                ldm_x4t(r, smb + bB + 8192 + SWZ256(kr, nb));
                bl[nfb][0] = r[0]; bl[nfb][1] = r[1];
                bl[nfb + 1][0] = r[2]; bl[nfb + 1][1] = r[3];
            }
#pragma unroll
            for (int mf = 0; mf < 4; mf++) {
                uint32_t ah[4], al[4];
                if (trA) {
                    const int kr = ks * 16 + klA;
                    const int mb = (wm * 64 + mf * 16) * 2 + mbA;
                    ldm_x4t(ah, smb + aB + SWZ256(kr, mb));
                    ldm_x4t(al, smb + aB + 8192 + SWZ256(kr, mb));
                } else {
                    const int rr = wm * 64 + mf * 16 + aRow;
                    const int kb = ks * 32 + aKB;
                    ldm_x4(ah, smb + aB + SWZ64(rr, kb));
                    ldm_x4(al, smb + aB + 8192 + SWZ64(rr, kb));
                }
#pragma unroll
                for (int nf = 0; nf < 4; nf++) {
                    mma16816(acc[mf][nf], ah, bh[nf]);
                    mma16816(acc[mf][nf], ah, bl[nf]);
                    mma16816(acc[mf][nf], al, bh[nf]);
                }
            }
        }
    };

    if (AF32) {
        // prologue: A(0) staged, A(1) in regs, B(0) and B(1) in flight
        ldgA(0);
        cpB(0, smb + 49152); CP_COMMIT();
        stsA(0);
        ldgA(1);
        cpB(1, smb + 49152 + 16384); CP_COMMIT();
        for (int c = 0; c < nch; c++) {
            if (c + 1 < nch) stsA(c + 1);
            __syncthreads();
            if (c + 2 < nch) {
                ldgA(c + 2);
                cpB(c + 2, smb + 49152 + ((c + 2) % 3) * 16384);
                CP_COMMIT();
                CP_WAIT2();
            } else if (c + 1 < nch) {
                CP_WAIT1();
            } else {
                CP_WAIT0();
            }
            compute_chunk((c % 3) * 16384u, 49152u + (c % 3) * 16384u);
        }
    } else {
        load_bf16(0, 0); CP_COMMIT();
        load_bf16(1, 1); CP_COMMIT();
        for (int c = 0; c < nch; c++) {
            if (c + 1 < nch) CP_WAIT1(); else CP_WAIT0();
            __syncthreads();
            if (c + 2 < nch) { load_bf16(c + 2, (c + 2) % 3); CP_COMMIT(); }
            compute_chunk((c % 3) * STAGEB, (c % 3) * STAGEB + 2 * MATB);
        }
    }

    if (OUTHL) {
#pragma unroll
        for (int mf = 0; mf < 4; mf++)
#pragma unroll
            for (int nf = 0; nf < 4; nf++) {
                const int mr0 = m0 + wm * 64 + mf * 16 + g, mr1 = mr0 + 8;
                const int n0 = wn * 32 + nf * 8 + 2 * t;
                const float* cc = acc[mf][nf];
                bf16 h0, l0, h1, l1, h2, l2, h3, l3;
                split2(cc[0], h0, l0); split2(cc[1], h1, l1);
                split2(cc[2], h2, l2); split2(cc[3], h3, l3);
                if (mr0 < A.Mvalid) {
                    *(uint32_t*)(A.Chi + z * A.sHL + (long)mr0 * 128 + n0) = pack_bf2(h0, h1);
                    *(uint32_t*)(A.Clo + z * A.sHL + (long)mr0 * 128 + n0) = pack_bf2(l0, l1);
                }
                if (mr1 < A.Mvalid) {
                    *(uint32_t*)(A.Chi + z * A.sHL + (long)mr1 * 128 + n0) = pack_bf2(h2, h3);
                    *(uint32_t*)(A.Clo + z * A.sHL + (long)mr1 * 128 + n0) = pack_bf2(l2, l3);
                }
            }
    }

    if (OUTS) {
        __syncthreads();
        float* part = (float*)sm;
#pragma unroll
        for (int mf = 0; mf < 4; mf++)
#pragma unroll
            for (int half = 0; half < 2; half++) {
                const int ml = wm * 64 + mf * 16 + half * 8 + g;
                const int mr = m0 + ml;
                float val = 0.f;
                if (mr < A.Mvalid) {
                    const bf16* uh = A.Uhi + z * A.sU + (long)mr * 128;
                    const bf16* ul = A.Ulo + z * A.sU + (long)mr * 128;
#pragma unroll
                    for (int nf = 0; nf < 4; nf++) {
                        const int n = wn * 32 + nf * 8 + 2 * t;
                        union { uint32_t u; bf16 h[2]; } H, L;
                        H.u = *(const uint32_t*)(uh + n);
                        L.u = *(const uint32_t*)(ul + n);
                        float u0 = __bfloat162float(H.h[0]) + __bfloat162float(L.h[0]);
                        float u1 = __bfloat162float(H.h[1]) + __bfloat162float(L.h[1]);
                        val += tanhf(u0 + acc[mf][nf][half * 2 + 0]) * s_wh[n];
                        val += tanhf(u1 + acc[mf][nf][half * 2 + 1]) * s_wh[n + 1];
                    }
                }
                val += __shfl_xor_sync(~0u, val, 1);
                val += __shfl_xor_sync(~0u, val, 2);
                if (t == 0) part[wn * 128 + ml] = val;
            }
        __syncthreads();
        if (tid < 128) {
            const int mr = m0 + tid;
            if (mr < A.Mvalid)
                A.Sout[z * A.sS + mr] =
                    part[tid] + part[128 + tid] + part[256 + tid] + part[384 + tid];
        }
    }
}

// ===================== tail =====================
__global__ void softmax2_kernel(float* __restrict__ svp, float* __restrict__ sqp)
{
    const bool isv = blockIdx.x < cfg::Bn;
    const int b = isv ? blockIdx.x : blockIdx.x - cfg::Bn;
    const int L = isv ? cfg::LV : cfg::LT;
    float* row = (isv ? svp : sqp) + (long)b * L;
    __shared__ float red[32];
    __shared__ float bval;
    const int tid = threadIdx.x, lane = tid & 31, wid = tid >> 5;
    const int nw = blockDim.x >> 5;
    float m = -1e30f;
    for (int i = tid; i < L; i += blockDim.x) m = fmaxf(m, row[i]);
#pragma unroll
    for (int o = 16; o > 0; o >>= 1) m = fmaxf(m, __shfl_xor_sync(~0u, m, o));
    if (lane == 0) red[wid] = m;
    __syncthreads();
    if (tid == 0) {
        float mm = red[0];
        for (int w = 1; w < nw; w++) mm = fmaxf(mm, red[w]);
        bval = mm;
    }
    __syncthreads();
    m = bval;
    __syncthreads();
    float sum = 0.f;
    for (int i = tid; i < L; i += blockDim.x) {
        float e = __expf(row[i] - m); row[i] = e; sum += e;
    }
#pragma unroll
    for (int o = 16; o > 0; o >>= 1) sum += __shfl_xor_sync(~0u, sum, o);
    if (lane == 0) red[wid] = sum;
    __syncthreads();
    if (tid == 0) {
        float ss = 0.f;
        for (int w = 0; w < nw; w++) ss += red[w];
        bval = ss;
    }
    __syncthreads();
    float inv = 1.f / bval;
    for (int i = tid; i < L; i += blockDim.x) row[i] *= inv;
}

__global__ void __launch_bounds__(768) context_part(
    const float* __restrict__ T, const float* __restrict__ I,
    const float* __restrict__ aq, const float* __restrict__ av,
    float* __restrict__ ctxp)
{
    constexpr int YS = cfg::LV / cfg::NP, XS = cfg::LT / cfg::NP;
    __shared__ float sq[XS];
    __shared__ float sv[YS];
    const int b = blockIdx.x, p = blockIdx.y, d = threadIdx.x;
    if (d < XS) sq[d] = aq[(long)b * cfg::LT + p * XS + d];
    if (d < YS) sv[d] = av[(long)b * cfg::LV + p * YS + d];
    __syncthreads();
    const float* Ib = I + (long)b * cfg::LV * cfg::E + (long)(p * YS) * cfg::E + d;
    const float* Tb = T + (long)b * cfg::LT * cfg::E + (long)(p * XS) * cfg::E + d;
    float acc = 0.f;
#pragma unroll 4
    for (int y = 0; y < YS; y++) acc += sv[y] * Ib[(long)y * cfg::E];
#pragma unroll 4
    for (int x = 0; x < XS; x++) acc += sq[x] * Tb[(long)x * cfg::E];
    ctxp[((long)b * cfg::NP + p) * cfg::E + d] = acc;
}

__global__ void __launch_bounds__(768) out_kernel(
    const float* __restrict__ ctxp, const float* __restrict__ ws,
    float* __restrict__ out)
{
    __shared__ float sc[cfg::E];
    const int b = blockIdx.x, e = threadIdx.x;
    float c = 0.f;
#pragma unroll
    for (int p = 0; p < cfg::NP; p++) c += ctxp[((long)b * cfg::NP + p) * cfg::E + e];
    sc[e] = c;
    __syncthreads();
    float acc = 0.f;
#pragma unroll 8
    for (int d = 0; d < cfg::E; d++) acc += sc[d] * ws[(long)d * cfg::E + e];
    out[(long)b * cfg::E + e] = tanhf(acc);
}

// ===================== launch =====================
extern "C" void kernel_launch(void* const* d_in, const int* in_sizes, int n_in,
                              void* d_out, int out_size)
{
    using namespace cfg;
    const float* T   = (const float*)d_in[0];
    const float* I   = (const float*)d_in[1];
    const float* wb  = (const float*)d_in[3];
    const float* wv  = (const float*)d_in[4];
    const float* wq  = (const float*)d_in[5];
    const float* whv = (const float*)d_in[6];
    const float* whq = (const float*)d_in[7];
    const float* ws  = (const float*)d_in[8];
    float* out = (float*)d_out;

#define GSA(v, s) cudaGetSymbolAddress((void**)&v, s)
    bf16 *wbhi, *wblo, *wqhi, *wqlo, *wvhi, *wvlo;
    bf16 *wqqhi, *wqqlo, *wvvhi, *wvvlo;
    bf16 *A1hi, *A1lo, *M1hi, *M1lo, *A2hi, *A2lo, *Hhi, *Hlo;
    float *sv, *sq, *ctxp;
    GSA(wbhi, g_wbhi); GSA(wblo, g_wblo);
    GSA(wqhi, g_wqhi); GSA(wqlo, g_wqlo); GSA(wvhi, g_wvhi); GSA(wvlo, g_wvlo);
    GSA(wqqhi, g_wqqhi); GSA(wqqlo, g_wqqlo); GSA(wvvhi, g_wvvhi); GSA(wvvlo, g_wvvlo);
    GSA(A1hi, g_A1hi); GSA(A1lo, g_A1lo); GSA(M1hi, g_M1hi); GSA(M1lo, g_M1lo);
    GSA(A2hi, g_A2hi); GSA(A2lo, g_A2lo); GSA(Hhi, g_Hhi); GSA(Hlo, g_Hlo);
    GSA(sv, g_sv); GSA(sq, g_sq); GSA(ctxp, g_ctxp);
#undef GSA

    cudaFuncSetAttribute(mma_gemm<true, true, false>,
        cudaFuncAttributeMaxDynamicSharedMemorySize, SMEM_MMA_BYTES);
    cudaFuncSetAttribute(mma_gemm<false, true, false>,
        cudaFuncAttributeMaxDynamicSharedMemorySize, SMEM_MMA_BYTES);
    cudaFuncSetAttribute(mma_gemm<true, false, true>,
        cudaFuncAttributeMaxDynamicSharedMemorySize, SMEM_MMA_BYTES);

    conv_flat<<<(E * E / 4 + 255) / 256, 256>>>(wb, wbhi, wblo, E * E / 4);
    conv_flat<<<(E * Kd / 4 + 255) / 256, 256>>>(wq, wqhi, wqlo, E * Kd / 4);
    conv_flat<<<(E * Kd / 4 + 255) / 256, 256>>>(wv, wvhi, wvlo, E * Kd / 4);

    GArgs Z{};

    // L1: wqq = T@wq | wvv = I@wv  (A fp32 flat)
    {
        GArgs a0 = Z, a1 = Z;
        a0.Af = T; a0.Bhi = wqhi; a0.Blo = wqlo;
        a0.Chi = wqqhi; a0.Clo = wqqlo;
        a0.Ktot = E; a0.Mvalid = Bn * LT; a0.Mclamp = Bn * LT;
        a1.Af = I; a1.Bhi = wvhi; a1.Blo = wvlo;
        a1.Chi = wvvhi; a1.Clo = wvvlo;
        a1.Ktot = E; a1.Mvalid = Bn * LV; a1.Mclamp = Bn * LV;
        mma_gemm<true, true, false><<<dim3(512 + 288, 1, 1), 256, SMEM_MMA_BYTES>>>(
            a0, a1, 512);
    }
    // L2: A1 = T^T@wqq | A2 = I^T@wvv  (A fp32 trans)
    {
        GArgs a0 = Z, a1 = Z;
        a0.Af = T; a0.sA = (long)LT * E; a0.transA = 1;
        a0.Bhi = wqqhi; a0.Blo = wqqlo; a0.sB = (long)LT * Kd;
        a0.Chi = A1hi; a0.Clo = A1lo; a0.sHL = (long)E * Kd;
        a0.Ktot = LT; a0.Mvalid = E; a0.Mclamp = E;
        a1.Af = I; a1.sA = (long)LV * E; a1.transA = 1;
        a1.Bhi = wvvhi; a1.Blo = wvvlo; a1.sB = (long)LV * Kd;
        a1.Chi = A2hi; a1.Clo = A2lo; a1.sHL = (long)E * Kd;
        a1.Ktot = LV; a1.Mvalid = E; a1.Mclamp = E;
        mma_gemm<true, true, false><<<dim3(12, 1, Bn), 256, SMEM_MMA_BYTES>>>(a0, a1, 6);
    }
    // L3: M1 = wb^T@A1 | H = wb@A2  (A bf16 hi/lo)
    {
        GArgs a0 = Z, a1 = Z;
        a0.Ahi = wbhi; a0.Alo = wblo; a0.transA = 1;
        a0.Bhi = A1hi; a0.Blo = A1lo; a0.sB = (long)E * Kd;
        a0.Chi = M1hi; a0.Clo = M1lo; a0.sHL = (long)E * Kd;
        a0.Ktot = E; a0.Mvalid = E;
        a1.Ahi = wbhi; a1.Alo = wblo; a1.transA = 0;
        a1.Bhi = A2hi; a1.Blo = A2lo; a1.sB = (long)E * Kd;
        a1.Chi = Hhi; a1.Clo = Hlo; a1.sHL = (long)E * Kd;
        a1.Ktot = E; a1.Mvalid = E;
        mma_gemm<false, true, false><<<dim3(12, 1, Bn), 256, SMEM_MMA_BYTES>>>(a0, a1, 6);
    }
    // L4: sv = score(I@M1 + wvv) | sq = score(T@H + wqq)  (A fp32, clamped)
    {
        GArgs a0 = Z, a1 = Z;
        a0.Af = I; a0.sA = (long)LV * E;
        a0.Bhi = M1hi; a0.Blo = M1lo; a0.sB = (long)E * Kd;
        a0.Uhi = wvvhi; a0.Ulo = wvvlo; a0.sU = (long)LV * Kd; a0.wh = whv;
        a0.Sout = sv; a0.sS = LV;
        a0.Ktot = E; a0.Mvalid = LV; a0.Mclamp = LV;
        a1.Af = T; a1.sA = (long)LT * E;
        a1.Bhi = Hhi; a1.Blo = Hlo; a1.sB = (long)E * Kd;
        a1.Uhi = wqqhi; a1.Ulo = wqqlo; a1.sU = (long)LT * Kd; a1.wh = whq;
        a1.Sout = sq; a1.sS = LT;
        a1.Ktot = E; a1.Mvalid = LT; a1.Mclamp = LT;
        mma_gemm<true, false, true><<<dim3(5 + 8, 1, Bn), 256, SMEM_MMA_BYTES>>>(a0, a1, 5);
    }

    softmax2_kernel<<<2 * Bn, 256>>>(sv, sq);
    context_part<<<dim3(Bn, NP), 768>>>(T, I, sq, sv, ctxp);
    out_kernel<<<Bn, 768>>>(ctxp, ws, out);
}

// round 16
// speedup vs baseline: 1.0427x; 1.0427x over previous
#include <cuda_runtime.h>
#include <cuda_bf16.h>
#include <math.h>
#include <stdint.h>

namespace cfg {
constexpr int Bn = 64, LT = 1024, LV = 576, E = 768, Kd = 128, NP = 8;
}
using bf16 = __nv_bfloat16;

__device__ __forceinline__ void split2(float v, bf16& h, bf16& l) {
    h = __float2bfloat16(v);
    l = __float2bfloat16(v - __bfloat162float(h));
}
__device__ __forceinline__ uint32_t pack_bf2(bf16 a, bf16 b) {
    union { bf16 h[2]; uint32_t u; } w; w.h[0] = a; w.h[1] = b; return w.u;
}
__device__ __forceinline__ void mma16816(float* d, const uint32_t* a, const uint32_t* b) {
    asm volatile("mma.sync.aligned.m16n8k16.row.col.f32.bf16.bf16.f32 "
        "{%0,%1,%2,%3}, {%4,%5,%6,%7}, {%8,%9}, {%0,%1,%2,%3};"
        : "+f"(d[0]), "+f"(d[1]), "+f"(d[2]), "+f"(d[3])
        : "r"(a[0]), "r"(a[1]), "r"(a[2]), "r"(a[3]), "r"(b[0]), "r"(b[1]));
}
__device__ __forceinline__ void ldm_x4(uint32_t* r, uint32_t sa) {
    asm volatile("ldmatrix.sync.aligned.m8n8.x4.shared.b16 {%0,%1,%2,%3}, [%4];"
        : "=r"(r[0]), "=r"(r[1]), "=r"(r[2]), "=r"(r[3]) : "r"(sa));
}
__device__ __forceinline__ void ldm_x4t(uint32_t* r, uint32_t sa) {
    asm volatile("ldmatrix.sync.aligned.m8n8.x4.trans.shared.b16 {%0,%1,%2,%3}, [%4];"
        : "=r"(r[0]), "=r"(r[1]), "=r"(r[2]), "=r"(r[3]) : "r"(sa));
}
__device__ __forceinline__ uint32_t smem_u32(const void* p) {
    uint32_t a;
    asm("{ .reg .u64 t; cvta.to.shared.u64 t, %1; cvt.u32.u64 %0, t; }" : "=r"(a) : "l"(p));
    return a;
}
#define CP_ASYNC16(s, g) \
    asm volatile("cp.async.cg.shared.global [%0], [%1], 16;" :: "r"(s), "l"(g))
#define CP_COMMIT() asm volatile("cp.async.commit_group;")
#define CP_WAIT1()  asm volatile("cp.async.wait_group 1;")
#define CP_WAIT0()  asm volatile("cp.async.wait_group 0;")

#define SWZ64(row, kb)  ((uint32_t)((row) * 64  + ((kb) ^ (((row) & 3) << 4))))
#define SWZ256(row, kb) ((uint32_t)((row) * 256 + ((kb) ^ (((row) & 7) << 4))))

// ===================== globals =====================
#define DEV_BF16(n, c) __device__ __align__(256) bf16 n[c]
DEV_BF16(g_wbhi, 768 * 768);       DEV_BF16(g_wblo, 768 * 768);
DEV_BF16(g_wqhi, 768 * 128);       DEV_BF16(g_wqlo, 768 * 128);
DEV_BF16(g_wvhi, 768 * 128);       DEV_BF16(g_wvlo, 768 * 128);
DEV_BF16(g_wqqhi, 64 * 1024 * 128); DEV_BF16(g_wqqlo, 64 * 1024 * 128);
DEV_BF16(g_wvvhi, 64 * 576 * 128);  DEV_BF16(g_wvvlo, 64 * 576 * 128);
DEV_BF16(g_A1hi, 64 * 768 * 128);   DEV_BF16(g_A1lo, 64 * 768 * 128);
DEV_BF16(g_M1hi, 64 * 768 * 128);   DEV_BF16(g_M1lo, 64 * 768 * 128);
DEV_BF16(g_A2hi, 64 * 768 * 128);   DEV_BF16(g_A2lo, 64 * 768 * 128);
DEV_BF16(g_Hhi, 64 * 768 * 128);    DEV_BF16(g_Hlo, 64 * 768 * 128);
__device__ float g_sv[cfg::Bn * cfg::LV];
__device__ float g_sq[cfg::Bn * cfg::LT];
__device__ float g_ctxp[cfg::Bn * cfg::NP * cfg::E];

// ===================== conversion (weights only) =====================
__global__ void conv_flat(const float* __restrict__ X,
                          bf16* __restrict__ hi, bf16* __restrict__ lo, long n4)
{
    long i = (long)blockIdx.x * blockDim.x + threadIdx.x;
    if (i >= n4) return;
    float4 v = ((const float4*)X)[i];
    union { bf16 h[4]; uint2 u; } H, L;
    split2(v.x, H.h[0], L.h[0]); split2(v.y, H.h[1], L.h[1]);
    split2(v.z, H.h[2], L.h[2]); split2(v.w, H.h[3], L.h[3]);
    ((uint2*)hi)[i] = H.u; ((uint2*)lo)[i] = L.u;
}

// ===================== merged-pair HMMA GEMM =====================
// AF32: A read as raw fp32, split to bf16 hi/lo in smem per chunk.
//   layout: [stage0 32K][stage1 32K][cb0 16K][cb1 16K]; stage=[Af32 16K|Bh 8K|Bl 8K]
// !AF32: A given as bf16 hi/lo (3-stage).
constexpr int MATB = 8192, STAGEB = 4 * MATB;
static constexpr int SMEM_MMA_BYTES = 98304;

struct GArgs {
    const float* Af;
    const bf16 *Ahi, *Alo;
    const bf16 *Bhi, *Blo;
    long sA, sB, sHL, sU, sS;
    bf16 *Chi, *Clo;
    const bf16 *Uhi, *Ulo;
    const float* wh;
    float* Sout;
    int Ktot, Mvalid, transA, Mclamp;
};

template <bool AF32, bool OUTHL, bool OUTS>
__global__ void __launch_bounds__(256, 2) mma_gemm(GArgs a0, GArgs a1, int splitX)
{
    extern __shared__ __align__(16) char sm[];
    __shared__ float s_wh[128];
    const uint32_t smb = smem_u32(sm);

    const GArgs& A = (blockIdx.x < (unsigned)splitX) ? a0 : a1;
    const int bx = (blockIdx.x < (unsigned)splitX) ? blockIdx.x : blockIdx.x - splitX;
    const int tid = threadIdx.x, lane = tid & 31, wid = tid >> 5;
    const int wm = wid & 1, wn = wid >> 1, g = lane >> 2, t = lane & 3;
    const long z = blockIdx.z;
    const int m0 = bx * 128, Ktot = A.Ktot;
    const bool trA = (A.transA != 0);

    if (OUTS && tid < 128) s_wh[tid] = A.wh[tid];

    const float* Af = nullptr;
    const bf16 *Ah = nullptr, *Al = nullptr;
    if (AF32) {
        Af = A.Af + z * A.sA;
    } else {
        Ah = A.Ahi + z * A.sA + (trA ? 0 : (long)m0 * 768);
        Al = A.Alo + z * A.sA + (trA ? 0 : (long)m0 * 768);
    }
    const bf16* Bh = A.Bhi + z * A.sB;
    const bf16* Bl = A.Blo + z * A.sB;

    float acc[4][4][4];
#pragma unroll
    for (int i = 0; i < 4; i++)
#pragma unroll
        for (int j = 0; j < 4; j++)
#pragma unroll
            for (int q = 0; q < 4; q++) acc[i][j][q] = 0.f;

    const int nch = Ktot >> 5;
    const int nr0 = (tid * 2) >> 2, nc0 = ((tid * 2) & 3) * 16;
    const int nr1 = (tid * 2 + 1) >> 2, nc1 = ((tid * 2 + 1) & 3) * 16;
    const int tr0 = (tid * 2) >> 4, tc0 = ((tid * 2) & 15) * 16;
    const int tr1 = (tid * 2 + 1) >> 4, tc1 = ((tid * 2 + 1) & 15) * 16;

    auto load_chunk = [&](int c, int stage) {
        const int k0 = c << 5;
        const uint32_t sb = smb + stage * 32768;
        if (AF32) {
            if (trA) {
#pragma unroll
                for (int j = 0; j < 4; j++) {
                    int u = tid + 256 * j;
                    int r = u >> 5, cu = u & 31;
                    CP_ASYNC16(sb + r * 512 + cu * 16,
                               Af + (long)(k0 + r) * 768 + m0 + cu * 4);
                }
            } else {
#pragma unroll
                for (int j = 0; j < 4; j++) {
                    int u = tid + 256 * j;
                    int r = u >> 3, cu = u & 7;
                    int rg = m0 + r; if (rg >= A.Mclamp) rg = A.Mclamp - 1;
                    CP_ASYNC16(sb + r * 128 + cu * 16,
                               Af + (long)rg * 768 + k0 + cu * 4);
                }
            }
            CP_ASYNC16(sb + 16384 + SWZ256(tr0, tc0), Bh + (long)(k0 + tr0) * 128 + tc0 / 2);
            CP_ASYNC16(sb + 16384 + SWZ256(tr1, tc1), Bh + (long)(k0 + tr1) * 128 + tc1 / 2);
            CP_ASYNC16(sb + 24576 + SWZ256(tr0, tc0), Bl + (long)(k0 + tr0) * 128 + tc0 / 2);
            CP_ASYNC16(sb + 24576 + SWZ256(tr1, tc1), Bl + (long)(k0 + tr1) * 128 + tc1 / 2);
        } else {
            if (trA) {
                CP_ASYNC16(sb + SWZ256(tr0, tc0), Ah + (long)(k0 + tr0) * 768 + m0 + tc0 / 2);
                CP_ASYNC16(sb + SWZ256(tr1, tc1), Ah + (long)(k0 + tr1) * 768 + m0 + tc1 / 2);
                CP_ASYNC16(sb + MATB + SWZ256(tr0, tc0), Al + (long)(k0 + tr0) * 768 + m0 + tc0 / 2);
                CP_ASYNC16(sb + MATB + SWZ256(tr1, tc1), Al + (long)(k0 + tr1) * 768 + m0 + tc1 / 2);
            } else {
                CP_ASYNC16(sb + SWZ64(nr0, nc0), Ah + (long)nr0 * 768 + k0 + nc0 / 2);
                CP_ASYNC16(sb + SWZ64(nr1, nc1), Ah + (long)nr1 * 768 + k0 + nc1 / 2);
                CP_ASYNC16(sb + MATB + SWZ64(nr0, nc0), Al + (long)nr0 * 768 + k0 + nc0 / 2);
                CP_ASYNC16(sb + MATB + SWZ64(nr1, nc1), Al + (long)nr1 * 768 + k0 + nc1 / 2);
            }
            CP_ASYNC16(sb + 2 * MATB + SWZ256(tr0, tc0), Bh + (long)(k0 + tr0) * 128 + tc0 / 2);
            CP_ASYNC16(sb + 2 * MATB + SWZ256(tr1, tc1), Bh + (long)(k0 + tr1) * 128 + tc1 / 2);
            CP_ASYNC16(sb + 3 * MATB + SWZ256(tr0, tc0), Bl + (long)(k0 + tr0) * 128 + tc0 / 2);
            CP_ASYNC16(sb + 3 * MATB + SWZ256(tr1, tc1), Bl + (long)(k0 + tr1) * 128 + tc1 / 2);
        }
    };

    auto convert = [&](int buf) {
        const char* fsrc = sm + buf * 32768;
        char* cb = sm + 65536 + buf * 16384;
#pragma unroll
        for (int j = 0; j < 4; j++) {
            int f = tid + 256 * j;
            int r, kb, soff;
            if (trA) { r = f >> 5; kb = (f & 31) * 8; soff = r * 512 + kb * 2; }
            else     { r = f >> 3; kb = (f & 7) * 8;  soff = r * 128 + kb * 2; }
            float4 v = *(const float4*)(fsrc + soff);
            union { bf16 b[4]; uint2 u; } H, L;
            split2(v.x, H.b[0], L.b[0]); split2(v.y, H.b[1], L.b[1]);
            split2(v.z, H.b[2], L.b[2]); split2(v.w, H.b[3], L.b[3]);
            uint32_t w = trA ? SWZ256(r, kb) : SWZ64(r, kb);
            *(uint2*)(cb + w) = H.u;
            *(uint2*)(cb + 8192 + w) = L.u;
        }
    };

    const int tr_r = lane & 7, tr_q = lane >> 3;
    const int klB = (tr_q & 1) * 8 + tr_r, nbB = (tr_q >> 1) * 16;
    const int klA = (tr_q >> 1) * 8 + tr_r, mbA = (tr_q & 1) * 16;
    const int aRow = (lane & 7) + ((lane >> 3) & 1) * 8, aKB = (lane >> 4) * 16;

    auto compute_chunk = [&](uint32_t aB, uint32_t bB) {
#pragma unroll
        for (int ks = 0; ks < 2; ks++) {
            uint32_t bh[4][2], bl[4][2];
#pragma unroll
            for (int nfb = 0; nfb < 4; nfb += 2) {
                const int kr = ks * 16 + klB;
                const int nb = (wn * 32 + nfb * 8) * 2 + nbB;
                uint32_t r[4];
                ldm_x4t(r, smb + bB + SWZ256(kr, nb));
                bh[nfb][0] = r[0]; bh[nfb][1] = r[1];
                bh[nfb + 1][0] = r[2]; bh[nfb + 1][1] = r[3];
                ldm_x4t(r, smb + bB + 8192 + SWZ256(kr, nb));
                bl[nfb][0] = r[0]; bl[nfb][1] = r[1];
                bl[nfb + 1][0] = r[2]; bl[nfb + 1][1] = r[3];
            }
#pragma unroll
            for (int mf = 0; mf < 4; mf++) {
                uint32_t ah[4], al[4];
                if (trA) {
                    const int kr = ks * 16 + klA;
                    const int mb = (wm * 64 + mf * 16) * 2 + mbA;
                    ldm_x4t(ah, smb + aB + SWZ256(kr, mb));
                    ldm_x4t(al, smb + aB + 8192 + SWZ256(kr, mb));
                } else {
                    const int rr = wm * 64 + mf * 16 + aRow;
                    const int kb = ks * 32 + aKB;
                    ldm_x4(ah, smb + aB + SWZ64(rr, kb));
                    ldm_x4(al, smb + aB + 8192 + SWZ64(rr, kb));
                }
#pragma unroll
                for (int nf = 0; nf < 4; nf++) {
                    mma16816(acc[mf][nf], ah, bh[nf]);
                    mma16816(acc[mf][nf], ah, bl[nf]);
                    mma16816(acc[mf][nf], al, bh[nf]);
                }
            }
        }
    };

    if (AF32) {
        load_chunk(0, 0); CP_COMMIT();
        for (int c = 0; c < nch; c++) {
            CP_WAIT0();
            __syncthreads();
            convert(c & 1);
            if (c + 1 < nch) { load_chunk(c + 1, (c + 1) & 1); CP_COMMIT(); }
            __syncthreads();
            compute_chunk(65536u + (c & 1) * 16384u, (c & 1) * 32768u + 16384u);
        }
    } else {
        load_chunk(0, 0); CP_COMMIT();
        load_chunk(1, 1); CP_COMMIT();
        for (int c = 0; c < nch; c++) {
            if (c + 1 < nch) CP_WAIT1(); else CP_WAIT0();
            __syncthreads();
            if (c + 2 < nch) { load_chunk(c + 2, (c + 2) % 3); CP_COMMIT(); }
            compute_chunk((c % 3) * STAGEB, (c % 3) * STAGEB + 2 * MATB);
        }
    }

    if (OUTHL) {
#pragma unroll
        for (int mf = 0; mf < 4; mf++)
#pragma unroll
            for (int nf = 0; nf < 4; nf++) {
                const int mr0 = m0 + wm * 64 + mf * 16 + g, mr1 = mr0 + 8;
                const int n0 = wn * 32 + nf * 8 + 2 * t;
                const float* cc = acc[mf][nf];
                bf16 h0, l0, h1, l1, h2, l2, h3, l3;
                split2(cc[0], h0, l0); split2(cc[1], h1, l1);
                split2(cc[2], h2, l2); split2(cc[3], h3, l3);
                if (mr0 < A.Mvalid) {
                    *(uint32_t*)(A.Chi + z * A.sHL + (long)mr0 * 128 + n0) = pack_bf2(h0, h1);
                    *(uint32_t*)(A.Clo + z * A.sHL + (long)mr0 * 128 + n0) = pack_bf2(l0, l1);
                }
                if (mr1 < A.Mvalid) {
                    *(uint32_t*)(A.Chi + z * A.sHL + (long)mr1 * 128 + n0) = pack_bf2(h2, h3);
                    *(uint32_t*)(A.Clo + z * A.sHL + (long)mr1 * 128 + n0) = pack_bf2(l2, l3);
                }
            }
    }

    if (OUTS) {
        __syncthreads();
        float* part = (float*)sm;
#pragma unroll
        for (int mf = 0; mf < 4; mf++)
#pragma unroll
            for (int half = 0; half < 2; half++) {
                const int ml = wm * 64 + mf * 16 + half * 8 + g;
                const int mr = m0 + ml;
                float val = 0.f;
                if (mr < A.Mvalid) {
                    const bf16* uh = A.Uhi + z * A.sU + (long)mr * 128;
                    const bf16* ul = A.Ulo + z * A.sU + (long)mr * 128;
#pragma unroll
                    for (int nf = 0; nf < 4; nf++) {
                        const int n = wn * 32 + nf * 8 + 2 * t;
                        union { uint32_t u; bf16 h[2]; } H, L;
                        H.u = *(const uint32_t*)(uh + n);
                        L.u = *(const uint32_t*)(ul + n);
                        float u0 = __bfloat162float(H.h[0]) + __bfloat162float(L.h[0]);
                        float u1 = __bfloat162float(H.h[1]) + __bfloat162float(L.h[1]);
                        val += tanhf(u0 + acc[mf][nf][half * 2 + 0]) * s_wh[n];
                        val += tanhf(u1 + acc[mf][nf][half * 2 + 1]) * s_wh[n + 1];
                    }
                }
                val += __shfl_xor_sync(~0u, val, 1);
                val += __shfl_xor_sync(~0u, val, 2);
                if (t == 0) part[wn * 128 + ml] = val;
            }
        __syncthreads();
        if (tid < 128) {
            const int mr = m0 + tid;
            if (mr < A.Mvalid)
                A.Sout[z * A.sS + mr] =
                    part[tid] + part[128 + tid] + part[256 + tid] + part[384 + tid];
        }
    }
}

// ===================== tail =====================
__global__ void softmax2_kernel(float* __restrict__ svp, float* __restrict__ sqp)
{
    const bool isv = blockIdx.x < cfg::Bn;
    const int b = isv ? blockIdx.x : blockIdx.x - cfg::Bn;
    const int L = isv ? cfg::LV : cfg::LT;
    float* row = (isv ? svp : sqp) + (long)b * L;
    __shared__ float red[32];
    __shared__ float bval;
    const int tid = threadIdx.x, lane = tid & 31, wid = tid >> 5;
    const int nw = blockDim.x >> 5;
    float m = -1e30f;
    for (int i = tid; i < L; i += blockDim.x) m = fmaxf(m, row[i]);
#pragma unroll
    for (int o = 16; o > 0; o >>= 1) m = fmaxf(m, __shfl_xor_sync(~0u, m, o));
    if (lane == 0) red[wid] = m;
    __syncthreads();
    if (tid == 0) {
        float mm = red[0];
        for (int w = 1; w < nw; w++) mm = fmaxf(mm, red[w]);
        bval = mm;
    }
    __syncthreads();
    m = bval;
    __syncthreads();
    float sum = 0.f;
    for (int i = tid; i < L; i += blockDim.x) {
        float e = __expf(row[i] - m); row[i] = e; sum += e;
    }
#pragma unroll
    for (int o = 16; o > 0; o >>= 1) sum += __shfl_xor_sync(~0u, sum, o);
    if (lane == 0) red[wid] = sum;
    __syncthreads();
    if (tid == 0) {
        float ss = 0.f;
        for (int w = 0; w < nw; w++) ss += red[w];
        bval = ss;
    }
    __syncthreads();
    float inv = 1.f / bval;
    for (int i = tid; i < L; i += blockDim.x) row[i] *= inv;
}

__global__ void __launch_bounds__(768) context_part(
    const float* __restrict__ T, const float* __restrict__ I,
    const float* __restrict__ aq, const float* __restrict__ av,
    float* __restrict__ ctxp)
{
    constexpr int YS = cfg::LV / cfg::NP, XS = cfg::LT / cfg::NP;
    __shared__ float sq[XS];
    __shared__ float sv[YS];
    const int b = blockIdx.x, p = blockIdx.y, d = threadIdx.x;
    if (d < XS) sq[d] = aq[(long)b * cfg::LT + p * XS + d];
    if (d < YS) sv[d] = av[(long)b * cfg::LV + p * YS + d];
    __syncthreads();
    const float* Ib = I + (long)b * cfg::LV * cfg::E + (long)(p * YS) * cfg::E + d;
    const float* Tb = T + (long)b * cfg::LT * cfg::E + (long)(p * XS) * cfg::E + d;
    float acc = 0.f;
#pragma unroll 4
    for (int y = 0; y < YS; y++) acc += sv[y] * Ib[(long)y * cfg::E];
#pragma unroll 4
    for (int x = 0; x < XS; x++) acc += sq[x] * Tb[(long)x * cfg::E];
    ctxp[((long)b * cfg::NP + p) * cfg::E + d] = acc;
}

__global__ void __launch_bounds__(768) out_kernel(
    const float* __restrict__ ctxp, const float* __restrict__ ws,
    float* __restrict__ out)
{
    __shared__ float sc[cfg::E];
    const int b = blockIdx.x, e = threadIdx.x;
    float c = 0.f;
#pragma unroll
    for (int p = 0; p < cfg::NP; p++) c += ctxp[((long)b * cfg::NP + p) * cfg::E + e];
    sc[e] = c;
    __syncthreads();
    float acc = 0.f;
#pragma unroll 8
    for (int d = 0; d < cfg::E; d++) acc += sc[d] * ws[(long)d * cfg::E + e];
    out[(long)b * cfg::E + e] = tanhf(acc);
}

// ===================== launch =====================
extern "C" void kernel_launch(void* const* d_in, const int* in_sizes, int n_in,
                              void* d_out, int out_size)
{
    using namespace cfg;
    const float* T   = (const float*)d_in[0];
    const float* I   = (const float*)d_in[1];
    const float* wb  = (const float*)d_in[3];
    const float* wv  = (const float*)d_in[4];
    const float* wq  = (const float*)d_in[5];
    const float* whv = (const float*)d_in[6];
    const float* whq = (const float*)d_in[7];
    const float* ws  = (const float*)d_in[8];
    float* out = (float*)d_out;

#define GSA(v, s) cudaGetSymbolAddress((void**)&v, s)
    bf16 *wbhi, *wblo, *wqhi, *wqlo, *wvhi, *wvlo;
    bf16 *wqqhi, *wqqlo, *wvvhi, *wvvlo;
    bf16 *A1hi, *A1lo, *M1hi, *M1lo, *A2hi, *A2lo, *Hhi, *Hlo;
    float *sv, *sq, *ctxp;
    GSA(wbhi, g_wbhi); GSA(wblo, g_wblo);
    GSA(wqhi, g_wqhi); GSA(wqlo, g_wqlo); GSA(wvhi, g_wvhi); GSA(wvlo, g_wvlo);
    GSA(wqqhi, g_wqqhi); GSA(wqqlo, g_wqqlo); GSA(wvvhi, g_wvvhi); GSA(wvvlo, g_wvvlo);
    GSA(A1hi, g_A1hi); GSA(A1lo, g_A1lo); GSA(M1hi, g_M1hi); GSA(M1lo, g_M1lo);
    GSA(A2hi, g_A2hi); GSA(A2lo, g_A2lo); GSA(Hhi, g_Hhi); GSA(Hlo, g_Hlo);
    GSA(sv, g_sv); GSA(sq, g_sq); GSA(ctxp, g_ctxp);
#undef GSA

    cudaFuncSetAttribute(mma_gemm<true, true, false>,
        cudaFuncAttributeMaxDynamicSharedMemorySize, SMEM_MMA_BYTES);
    cudaFuncSetAttribute(mma_gemm<false, true, false>,
        cudaFuncAttributeMaxDynamicSharedMemorySize, SMEM_MMA_BYTES);
    cudaFuncSetAttribute(mma_gemm<true, false, true>,
        cudaFuncAttributeMaxDynamicSharedMemorySize, SMEM_MMA_BYTES);

    conv_flat<<<(E * E / 4 + 255) / 256, 256>>>(wb, wbhi, wblo, E * E / 4);
    conv_flat<<<(E * Kd / 4 + 255) / 256, 256>>>(wq, wqhi, wqlo, E * Kd / 4);
    conv_flat<<<(E * Kd / 4 + 255) / 256, 256>>>(wv, wvhi, wvlo, E * Kd / 4);

    GArgs Z{};

    // L1: wqq = T@wq | wvv = I@wv  (A fp32 flat)
    {
        GArgs a0 = Z, a1 = Z;
        a0.Af = T; a0.Bhi = wqhi; a0.Blo = wqlo;
        a0.Chi = wqqhi; a0.Clo = wqqlo;
        a0.Ktot = E; a0.Mvalid = Bn * LT; a0.Mclamp = Bn * LT;
        a1.Af = I; a1.Bhi = wvhi; a1.Blo = wvlo;
        a1.Chi = wvvhi; a1.Clo = wvvlo;
        a1.Ktot = E; a1.Mvalid = Bn * LV; a1.Mclamp = Bn * LV;
        mma_gemm<true, true, false><<<dim3(512 + 288, 1, 1), 256, SMEM_MMA_BYTES>>>(
            a0, a1, 512);
    }
    // L2: A1 = T^T@wqq | A2 = I^T@wvv  (A fp32 trans)
    {
        GArgs a0 = Z, a1 = Z;
        a0.Af = T; a0.sA = (long)LT * E; a0.transA = 1;
        a0.Bhi = wqqhi; a0.Blo = wqqlo; a0.sB = (long)LT * Kd;
        a0.Chi = A1hi; a0.Clo = A1lo; a0.sHL = (long)E * Kd;
        a0.Ktot = LT; a0.Mvalid = E; a0.Mclamp = E;
        a1.Af = I; a1.sA = (long)LV * E; a1.transA = 1;
        a1.Bhi = wvvhi; a1.Blo = wvvlo; a1.sB = (long)LV * Kd;
        a1.Chi = A2hi; a1.Clo = A2lo; a1.sHL = (long)E * Kd;
        a1.Ktot = LV; a1.Mvalid = E; a1.Mclamp = E;
        mma_gemm<true, true, false><<<dim3(12, 1, Bn), 256, SMEM_MMA_BYTES>>>(a0, a1, 6);
    }
    // L3: M1 = wb^T@A1 | H = wb@A2  (A bf16 hi/lo)
    {
        GArgs a0 = Z, a1 = Z;
        a0.Ahi = wbhi; a0.Alo = wblo; a0.transA = 1;
        a0.Bhi = A1hi; a0.Blo = A1lo; a0.sB = (long)E * Kd;
        a0.Chi = M1hi; a0.Clo = M1lo; a0.sHL = (long)E * Kd;
        a0.Ktot = E; a0.Mvalid = E;
        a1.Ahi = wbhi; a1.Alo = wblo; a1.transA = 0;
        a1.Bhi = A2hi; a1.Blo = A2lo; a1.sB = (long)E * Kd;
        a1.Chi = Hhi; a1.Clo = Hlo; a1.sHL = (long)E * Kd;
        a1.Ktot = E; a1.Mvalid = E;
        mma_gemm<false, true, false><<<dim3(12, 1, Bn), 256, SMEM_MMA_BYTES>>>(a0, a1, 6);
    }
    // L4: sv = score(I@M1 + wvv) | sq = score(T@H + wqq)  (A fp32, clamped)
    {
        GArgs a0 = Z, a1 = Z;
        a0.Af = I; a0.sA = (long)LV * E;
        a0.Bhi = M1hi; a0.Blo = M1lo; a0.sB = (long)E * Kd;
        a0.Uhi = wvvhi; a0.Ulo = wvvlo; a0.sU = (long)LV * Kd; a0.wh = whv;
        a0.Sout = sv; a0.sS = LV;
        a0.Ktot = E; a0.Mvalid = LV; a0.Mclamp = LV;
        a1.Af = T; a1.sA = (long)LT * E;
        a1.Bhi = Hhi; a1.Blo = Hlo; a1.sB = (long)E * Kd;
        a1.Uhi = wqqhi; a1.Ulo = wqqlo; a1.sU = (long)LT * Kd; a1.wh = whq;
        a1.Sout = sq; a1.sS = LT;
        a1.Ktot = E; a1.Mvalid = LT; a1.Mclamp = LT;
        mma_gemm<true, false, true><<<dim3(5 + 8, 1, Bn), 256, SMEM_MMA_BYTES>>>(a0, a1, 5);
    }

    softmax2_kernel<<<2 * Bn, 256>>>(sv, sq);
    context_part<<<dim3(Bn, NP), 768>>>(T, I, sq, sv, ctxp);
    out_kernel<<<Bn, 768>>>(ctxp, ws, out);
}